// round 5
// baseline (speedup 1.0000x reference)
#include <cuda_runtime.h>
#include <cstddef>

#define NEG (-1e20f)

constexpr int NA = 512;     // rows
constexpr int NB = 1024;    // cols
constexpr int NW = 16;      // warps per CTA (each owns 32 cols)
constexpr int NT = NW * 32; // 512 threads
constexpr int WDEP = 48;    // W smem ring depth (rows)
constexpr int ODEP = 48;    // out smem ring depth (rows)
constexpr int BDEP = 128;   // intra-CTA boundary ring depth
constexpr int BP_SLACK = 112; // backpressure: max producer-consumer tick skew
constexpr int GDEP = 16;    // cross-CTA prefetch ring depth
constexpr int TICKS = 552;  // last active tick 543; last flush tick 552

constexpr size_t BRING_B = (size_t)NW * BDEP * 8;
constexpr size_t WRING_F = (size_t)NW * WDEP * 32;
constexpr size_t ORING_F = (size_t)NW * ODEP * 32;
constexpr size_t SMEM_B  = BRING_B + (WRING_F + ORING_F + GDEP) * 4 + NW * 4;

// cross-CTA boundary: [batch][row] tagged values, indexed by row (no wrap).
// Tags are row indices (>=1); zero-init at load. Values replay-deterministic.
__device__ volatile unsigned long long gbnd[32][NA + 8];

__device__ __forceinline__ float lse3(float a, float b, float c) {
    float m = fmaxf(a, fmaxf(b, c));
    float s = __expf(a - m) + __expf(b - m) + __expf(c - m);
    return m + __logf(s);
}
__device__ __forceinline__ unsigned long long packsv(int s, float v) {
    return ((unsigned long long)(unsigned)s << 32) | (unsigned long long)__float_as_uint(v);
}

__global__ void __launch_bounds__(NT, 1)
dtw_stagger_kernel(const float* __restrict__ W, float* __restrict__ out) {
    extern __shared__ unsigned char sm[];
    volatile unsigned long long* bring = (volatile unsigned long long*)sm; // [NW][BDEP]
    float* wring = (float*)(sm + BRING_B);   // [NW][WDEP][32]
    float* oring = wring + WRING_F;          // [NW][ODEP][32]
    float* gring = oring + ORING_F;          // [GDEP]
    volatile int* prog = (volatile int*)(gring + GDEP);  // [NW] consumer tick

    const int b    = blockIdx.x >> 1;
    const int c    = blockIdx.x & 1;         // CTA half: cols [512c+1 .. 512c+512]
    const int t    = threadIdx.x;
    const int lane = t & 31;
    const int wl   = t >> 5;                 // local warp
    const int g    = c * NW + wl;            // global warp 0..31
    const int c0   = g << 5;                 // lane col j = c0 + lane + 1

    const float* Wb = W + (size_t)b * NA * NB;
    float* Ob = out + (size_t)b * (NA + 1) * (NB + 1);

    // ---- edge outputs ----
    if (c == 0) {
        Ob[t] = (t == 0) ? 0.0f : NEG;                 // row 0, cols 0..511
        if (t == 0) Ob[512] = NEG;                     // row 0, col 512
        Ob[(size_t)(t + 1) * (NB + 1)] = NEG;          // col 0, rows 1..512
    } else {
        Ob[512 + t] = NEG;                             // row 0, cols 512..1023
        if (t == 0) Ob[1024] = NEG;                    // row 0, col 1024
    }
    // init boundary ring tags (rows are >=1) and progress counters
    for (int k = t; k < NW * BDEP; k += NT) bring[k] = 0ull;
    if (t < NW) prog[t] = 0;
    __syncthreads();   // the only block barrier

    // ---- prefill W rows 0..15 (coalesced) ----
    #pragma unroll
    for (int f = 0; f < 16; ++f)
        wring[(wl * WDEP + f) * 32 + lane] = Wb[f * NB + c0 + lane];

    // ---- CTA1 wl0: prefill cross-CTA boundary rows 1..15 ----
    if (c == 1 && wl == 0) {
        if (lane >= 1 && lane <= 15) {
            int r = lane;
            unsigned long long p = gbnd[b][r];
            while ((int)(p >> 32) != r) { __nanosleep(128); p = gbnd[b][r]; }
            gring[r & (GDEP - 1)] = __uint_as_float((unsigned)p);
        }
        __syncwarp();
    }

    float v1    = NEG;                                  // mu[i-1][j] (this lane)
    float lprev = (g == 0 && lane == 0) ? 0.0f : NEG;   // upper-left carry

    auto step = [&](int tt) {
        const int  i   = tt - lane;                 // row this lane computes
        const bool act = (i >= 1) && (i <= NA);

        float lv = __shfl_up_sync(0xFFFFFFFFu, v1, 1);   // mu[i][j-1]
        if (lane == 0) {
            lv = NEG;
            if (act && g > 0) {
                if (wl > 0) {
                    volatile unsigned long long* slot =
                        &bring[(wl - 1) * BDEP + (tt & (BDEP - 1))];
                    unsigned long long p = *slot;
                    if ((int)(p >> 32) != tt) {
                        do { __nanosleep(32); p = *slot; } while ((int)(p >> 32) != tt);
                    }
                    lv = __uint_as_float((unsigned)p);
                } else {
                    lv = gring[tt & (GDEP - 1)];    // prefetched, tag pre-verified
                }
            }
        }
        float ul = lprev;                           // mu[i-1][j-1]

        if (act) {
            float w = wring[(wl * WDEP + ((i - 1) % WDEP)) * 32 + lane];
            float v = lse3(v1, lv, ul) + w;
            oring[(wl * ODEP + (i % ODEP)) * 32 + lane] = v;
            v1 = v;
            if (lane == 31) {
                if (wl < NW - 1)
                    bring[wl * BDEP + (i & (BDEP - 1))] = packsv(i, v);
                else if (c == 0)
                    gbnd[b][i] = packsv(i, v);      // hand off to CTA1
            }
        }
        lprev = lv;
    };

    // ---- ticks 1..7 (no maintenance) ----
    #pragma unroll
    for (int tt = 1; tt <= 7; ++tt) step(tt);

    // ---- 8-tick blocks with maintenance at block head ----
    for (int m = 8; m <= TICKS; m += 8) {
        // publish our progress (ticks < m complete)
        if (lane == 0) prog[wl] = m;

        // backpressure: don't let our boundary ring lap the consumer
        if (wl < NW - 1) {
            if (m - prog[wl + 1] > BP_SLACK) {
                do { __nanosleep(64); } while (m - prog[wl + 1] > BP_SLACK);
            }
        }

        // fill W rows m+8 .. m+15 (coalesced)
        #pragma unroll
        for (int f = 0; f < 8; ++f) {
            int r = m + 8 + f;
            if (r < NA)
                wring[(wl * WDEP + (r % WDEP)) * 32 + lane] = Wb[r * NB + c0 + lane];
        }
        // flush completed output rows m-46 .. m-39 (coalesced)
        #pragma unroll
        for (int f = 0; f < 8; ++f) {
            int r = m - 46 + f;
            if (r >= 1 && r <= NA)
                Ob[(size_t)r * (NB + 1) + c0 + 1 + lane] =
                    oring[(wl * ODEP + (r % ODEP)) * 32 + lane];
        }
        // CTA1 wl0: prefetch boundary rows m+8 .. m+15 from global
        if (c == 1 && wl == 0) {
            if (lane < 8) {
                int r = m + 8 + lane;
                if (r <= NA) {
                    unsigned long long p = gbnd[b][r];
                    while ((int)(p >> 32) != r) { __nanosleep(128); p = gbnd[b][r]; }
                    gring[r & (GDEP - 1)] = __uint_as_float((unsigned)p);
                }
            }
            __syncwarp();
        }

        #pragma unroll
        for (int u = 0; u < 8; ++u) step(m + u);
    }
}

extern "C" void kernel_launch(void* const* d_in, const int* in_sizes, int n_in,
                              void* d_out, int out_size) {
    const float* W = (const float*)d_in[0];
    float* out = (float*)d_out;
    cudaFuncSetAttribute(dtw_stagger_kernel,
                         cudaFuncAttributeMaxDynamicSharedMemorySize,
                         (int)SMEM_B);
    dtw_stagger_kernel<<<64, NT, SMEM_B>>>(W, out);
}

// round 6
// speedup vs baseline: 1.7340x; 1.7340x over previous
#include <cuda_runtime.h>
#include <cstddef>

#define NEGF (-1e20f)

constexpr int NA   = 512;           // rows i = 1..512
constexpr int NBC  = 1024;          // cols j = 1..1024
constexpr int TPC  = 8;             // columns per thread
constexpr int NT   = NBC / TPC;     // 128 threads, 4 warps
constexpr int STEPS = NA + NT - 1;  // 639
constexpr int E_NEG = -(1 << 28);   // exponent of "-inf" cells (mantissa 0)

// 2^d as float: exact for d in [-126, 170]; 0 for very negative d (NEG cells).
__device__ __forceinline__ float p2(int d) {
    int k = d + 127;
    k = max(k, 0);
    return __int_as_float(k << 23);
}

__global__ void __launch_bounds__(NT, 1)
dtw_linear_kernel(const float* __restrict__ W, float* __restrict__ out) {
    __shared__ unsigned long long bnd[2][4];   // [step parity][warp] packed (e,m)

    const int b    = blockIdx.x;
    const int t    = threadIdx.x;
    const int lane = t & 31;
    const int w    = t >> 5;

    const float* Wb = W + (size_t)b * NA * NBC;
    float* Ob = out + (size_t)b * (NA + 1) * (NBC + 1);

    // ---- edge outputs ----
    for (int k = t; k <= NBC; k += NT) Ob[k] = (k == 0) ? 0.0f : NEGF;
    for (int r = t + 1; r <= NA; r += NT) Ob[(size_t)r * (NBC + 1)] = NEGF;

    // ---- state: top row values (mantissa, exponent) = row 0 = NEG ----
    float tm[TPC]; int te[TPC];
    #pragma unroll
    for (int k = 0; k < TPC; ++k) { tm[k] = 0.0f; te[k] = E_NEG; }
    float pm = 0.0f; int pe = E_NEG;   // lprev: neighbor col-8t value from step s-2

    // ---- W double-buffer: at step s consume buf[s&1], reload it for s+2 ----
    float4 bufA[2], bufB[2];
    {
        int r1 = 0 - t;                            // row for s=1
        if ((unsigned)r1 < (unsigned)NA) {
            const float4* p = (const float4*)(Wb + (size_t)r1 * NBC + TPC * t);
            bufA[1] = p[0]; bufB[1] = p[1];
        }
        int r2 = 1 - t;                            // row for s=2
        if ((unsigned)r2 < (unsigned)NA) {
            const float4* p = (const float4*)(Wb + (size_t)r2 * NBC + TPC * t);
            bufA[0] = p[0]; bufB[0] = p[1];
        }
    }

    for (int s = 1; s <= STEPS; ++s) {
        __syncthreads();   // orders previous step's bnd writes before this step's reads

        const int  i   = s - t;                    // row this thread computes
        const bool act = (unsigned)(i - 1) < (unsigned)NA;

        // neighbor's col (8t) value for row i (computed by t-1 at step s-1)
        float lvm = __shfl_up_sync(0xFFFFFFFFu, tm[TPC - 1], 1);
        int   lve = __shfl_up_sync(0xFFFFFFFFu, te[TPC - 1], 1);
        if (lane == 0 && w > 0) {
            unsigned long long pk = bnd[s & 1][w - 1];
            lvm = __uint_as_float((unsigned)pk);
            lve = (int)(pk >> 32);
        }
        if (t == 0) { lvm = 0.0f; lve = E_NEG; }   // col 0 = NEG (mantissa 0)

        // diag for first cell = lprev; row-0 override at i==1
        float dm = pm; int de = pe;
        if (i == 1) {
            dm = (t == 0) ? 1.0f : 0.0f;           // mu[0][0]=0 -> (1,0); else NEG
            de = (t == 0) ? 0    : E_NEG;
        }
        pm = lvm; pe = lve;                         // becomes diag at step s+1

        if (act) {
            const float4 A = bufA[s & 1];
            const float4 B = bufB[s & 1];
            float wv[TPC] = {A.x, A.y, A.z, A.w, B.x, B.y, B.z, B.w};

            int e_base = max(lve, max(te[0], de));
            float leftm = lvm * p2(lve - e_base);   // left-in, rescaled to e_base

            float* orow = Ob + (size_t)i * (NBC + 1) + TPC * t + 1;
            float prev_m = dm; int prev_e = de;     // diag input (old top of col k-1)

            #pragma unroll
            for (int k = 0; k < TPC; ++k) {
                float f  = __expf(wv[k]);           // e^W, off-chain
                float pt = p2(te[k]  - e_base);
                float pd = p2(prev_e - e_base);
                float sacc = fmaf(tm[k], pt, fmaf(prev_m, pd, leftm));
                leftm = sacc * f;                   // in-step chain: FFMA+FMUL only

                prev_m = tm[k]; prev_e = te[k];     // save old top -> next diag

                // renormalize for storage as new top
                int bits = __float_as_int(leftm);
                int ee   = (bits >> 23) - 127;
                tm[k] = __int_as_float((bits & 0x007FFFFF) | 0x3F800000);
                te[k] = e_base + ee;

                // log-domain output: mu = (e + log2 m) * ln2
                orow[k] = ((float)te[k] + __log2f(tm[k])) * 0.69314718056f;
            }
        }

        // reload W for step s+2 (row i+1)
        if ((unsigned)(i + 1) < (unsigned)NA) {
            const float4* p = (const float4*)(Wb + (size_t)(i + 1) * NBC + TPC * t);
            bufA[s & 1] = p[0]; bufB[s & 1] = p[1];
        }

        // publish boundary value (col 8t+8, row i) for next step's consumer
        if (lane == 31) {
            bnd[(s + 1) & 1][w] =
                ((unsigned long long)(unsigned)te[TPC - 1] << 32) |
                (unsigned long long)__float_as_uint(tm[TPC - 1]);
        }
    }
}

extern "C" void kernel_launch(void* const* d_in, const int* in_sizes, int n_in,
                              void* d_out, int out_size) {
    const float* W = (const float*)d_in[0];
    float* out = (float*)d_out;
    dtw_linear_kernel<<<32, NT>>>(W, out);
}